// round 2
// baseline (speedup 1.0000x reference)
#include <cuda_runtime.h>
#include <math.h>

// Problem constants: B=2, N=4096, D=256, H=64, K=16
#define NPTS   4096
#define BNTOT  8192
#define DIM    256
#define HID    64
#define KNB    16
#define OUT_ATTN_OFF 2097152  // 2*4096*256

// ---------------- device scratch (no cudaMalloc allowed) ----------------
__device__ float d_Wstack[768 * 256];   // rows 0-255: W_alpha ; 256-511: A=Wg1*Wphi ; 512-767: Bm=Wg1*Wpsi
__device__ float d_Wg2T[256 * 256];     // Wg2T[i][d] = W_g2[d][i]
__device__ float d_Wp2T[64 * 256];      // Wp2T[h][d] = W_p2[d][h]
__device__ float d_CT[64 * 256];        // CT[h][d]   = (Wg1*Wp2)[d][h]
__device__ float d_biash[256];          // b_g1 + Wg1*(b_p2 + b_phi - b_psi)
__device__ float d_nodebuf[8192 * 768]; // per node: [v(256) | qg(256) | kg(256)]
__device__ int   d_knn[8192 * 16];

// ---------------- weight folding ----------------
__global__ void k_fold_AB(const float* __restrict__ Wg1,
                          const float* __restrict__ Wphi,
                          const float* __restrict__ Wpsi) {
    __shared__ float row[256];
    int r = blockIdx.x, t = threadIdx.x;
    int src = (r < 256) ? r : r - 256;
    row[t] = Wg1[src * 256 + t];
    __syncthreads();
    const float* W = (r < 256) ? Wphi : Wpsi;
    float acc = 0.f;
    for (int i = 0; i < 256; i++) acc += row[i] * W[i * 256 + t];
    d_Wstack[(256 + r) * 256 + t] = acc;
}

__global__ void k_fold_copy(const float* __restrict__ Walpha,
                            const float* __restrict__ Wg2,
                            const float* __restrict__ Wp2) {
    int blk = blockIdx.x, t = threadIdx.x;
    if (blk < 256) {
        d_Wstack[blk * 256 + t] = Walpha[blk * 256 + t];
    } else if (blk < 512) {
        int dd = blk - 256;
        d_Wg2T[t * 256 + dd] = Wg2[dd * 256 + t];
    } else {
        int idx = (blk - 512) * 256 + t;   // over 256*64 elements
        int dd = idx >> 6, h = idx & 63;
        d_Wp2T[h * 256 + dd] = Wp2[idx];   // Wp2[dd][h]
    }
}

__global__ void k_fold_C(const float* __restrict__ Wg1,
                         const float* __restrict__ Wp2) {
    __shared__ float row[256];
    int o = blockIdx.x, hh = threadIdx.x;  // 64 threads
    for (int i = hh; i < 256; i += 64) row[i] = Wg1[o * 256 + i];
    __syncthreads();
    float acc = 0.f;
    for (int tt = 0; tt < 256; tt++) acc += row[tt] * Wp2[tt * 64 + hh];
    d_CT[hh * 256 + o] = acc;
}

__global__ void k_fold_bias(const float* __restrict__ Wg1,
                            const float* __restrict__ bg1,
                            const float* __restrict__ bphi,
                            const float* __restrict__ bpsi,
                            const float* __restrict__ bp2) {
    __shared__ float combo[256];
    int t = threadIdx.x;
    combo[t] = bp2[t] + bphi[t] - bpsi[t];
    __syncthreads();
    float acc = bg1[t];
    for (int i = 0; i < 256; i++) acc += Wg1[t * 256 + i] * combo[i];
    d_biash[t] = acc;
}

// ---------------- KNN: brute force top-16 ----------------
__global__ void knn_kernel(const float* __restrict__ xyz) {
    __shared__ float tx[256], tys[256], tz[256], tsq[256];
    int gq = blockIdx.x * 128 + threadIdx.x;   // 0..8191
    int b = gq >> 12;
    float qx = xyz[gq * 3 + 0], qy = xyz[gq * 3 + 1], qz = xyz[gq * 3 + 2];
    float sqq = qx * qx + qy * qy + qz * qz;
    float bd[16];
    int   bi[16];
#pragma unroll
    for (int j = 0; j < 16; j++) { bd[j] = 3.4e38f; bi[j] = 0x7fffffff; }

    for (int tile = 0; tile < 16; tile++) {
        int base = tile * 256;
        __syncthreads();
        for (int s = threadIdx.x; s < 256; s += 128) {
            int g = (b << 12) + base + s;
            float x = xyz[g * 3 + 0], y = xyz[g * 3 + 1], z = xyz[g * 3 + 2];
            tx[s] = x; tys[s] = y; tz[s] = z;
            tsq[s] = x * x + y * y + z * z;
        }
        __syncthreads();
        for (int s = 0; s < 256; s++) {
            float dot = qx * tx[s] + qy * tys[s] + qz * tz[s];
            float d2 = sqq + tsq[s] - 2.f * dot;
            int m = base + s;
            if (d2 < bd[15] || (d2 == bd[15] && m < bi[15])) {
                bd[15] = d2; bi[15] = m;
#pragma unroll
                for (int u = 15; u >= 1; --u) {
                    bool sw = bd[u] < bd[u - 1] || (bd[u] == bd[u - 1] && bi[u] < bi[u - 1]);
                    if (sw) {
                        float td = bd[u]; bd[u] = bd[u - 1]; bd[u - 1] = td;
                        int ti = bi[u];  bi[u] = bi[u - 1];  bi[u - 1] = ti;
                    }
                }
            }
        }
    }
#pragma unroll
    for (int j = 0; j < 16; j++) d_knn[gq * 16 + j] = bi[j];
}

// ---------------- per-node GEMM: nodebuf = feat @ Wstack^T (+bias on v block) ----------------
__global__ void node_gemm(const float* __restrict__ feat,
                          const float* __restrict__ balpha) {
    __shared__ float As[16][68];
    __shared__ float Bs[16][68];
    int tx = threadIdx.x, ty = threadIdx.y;
    int t = ty * 16 + tx;
    int o0 = blockIdx.x * 64, m0 = blockIdx.y * 64;
    float acc[4][4] = {};
    int lm = t >> 2, lk = (t & 3) * 4;
    for (int k0 = 0; k0 < 256; k0 += 16) {
        float4 fa = *(const float4*)&feat[(m0 + lm) * 256 + k0 + lk];
        float4 fb = *(const float4*)&d_Wstack[(o0 + lm) * 256 + k0 + lk];
        __syncthreads();
        As[lk + 0][lm] = fa.x; As[lk + 1][lm] = fa.y; As[lk + 2][lm] = fa.z; As[lk + 3][lm] = fa.w;
        Bs[lk + 0][lm] = fb.x; Bs[lk + 1][lm] = fb.y; Bs[lk + 2][lm] = fb.z; Bs[lk + 3][lm] = fb.w;
        __syncthreads();
#pragma unroll
        for (int kk = 0; kk < 16; kk++) {
            float4 a = *(const float4*)&As[kk][ty * 4];
            float4 bb = *(const float4*)&Bs[kk][tx * 4];
            acc[0][0] += a.x * bb.x; acc[0][1] += a.x * bb.y; acc[0][2] += a.x * bb.z; acc[0][3] += a.x * bb.w;
            acc[1][0] += a.y * bb.x; acc[1][1] += a.y * bb.y; acc[1][2] += a.y * bb.z; acc[1][3] += a.y * bb.w;
            acc[2][0] += a.z * bb.x; acc[2][1] += a.z * bb.y; acc[2][2] += a.z * bb.z; acc[2][3] += a.z * bb.w;
            acc[3][0] += a.w * bb.x; acc[3][1] += a.w * bb.y; acc[3][2] += a.w * bb.z; acc[3][3] += a.w * bb.w;
        }
    }
#pragma unroll
    for (int i = 0; i < 4; i++) {
        int m = m0 + ty * 4 + i;
#pragma unroll
        for (int j = 0; j < 4; j++) {
            int o = o0 + tx * 4 + j;
            float bias = (o < 256) ? balpha[o] : 0.f;
            d_nodebuf[m * 768 + o] = acc[i][j] + bias;
        }
    }
}

// ---------------- main fused attention kernel: one block per (b,n) ----------------
__global__ void __launch_bounds__(256) pt_main_kernel(
    const float* __restrict__ xyz,
    const float* __restrict__ Wp1, const float* __restrict__ bp1,
    const float* __restrict__ bp2, const float* __restrict__ bg2,
    float* __restrict__ out) {
    __shared__ __align__(16) float pe1s[64 * 16];   // pe1s[h][j]
    __shared__ __align__(16) float h1s[256 * 20];   // h1s[i][j], stride 20 (80B, 16B-aligned rows)
    __shared__ float nx[16], ny[16], nz[16];
    __shared__ int idxs[16];
    __shared__ float q3[3];

    int g = blockIdx.x;      // global point 0..8191
    int b = g >> 12;
    int t = threadIdx.x;     // channel d

    if (t < 16) idxs[t] = d_knn[g * 16 + t];
    if (t < 3)  q3[t] = xyz[g * 3 + t];
    __syncthreads();
    if (t < 48) {
        int j = t / 3, c = t % 3;
        float v = xyz[((b << 12) + idxs[j]) * 3 + c];
        if (c == 0) nx[j] = v; else if (c == 1) ny[j] = v; else nz[j] = v;
    }
    __syncthreads();

    // phase B: pe1[j][h] = relu(W_p1 rel + b_p1)
#pragma unroll
    for (int r = 0; r < 4; r++) {
        int idx = r * 256 + t;
        int j = idx & 15, hh = idx >> 4;
        float rx = q3[0] - nx[j], ry = q3[1] - ny[j], rz = q3[2] - nz[j];
        float v = bp1[hh] + Wp1[hh * 3 + 0] * rx + Wp1[hh * 3 + 1] * ry + Wp1[hh * 3 + 2] * rz;
        pe1s[hh * 16 + j] = fmaxf(v, 0.f);
    }
    __syncthreads();

    // phase C: pos[j] = W_p2 pe1 (+b_p2), cc[j] = C pe1 ; then h1 = relu(cc + qg - kg + bias_h)
    float pos[16], cc[16];
#pragma unroll
    for (int j = 0; j < 16; j++) { pos[j] = 0.f; cc[j] = 0.f; }
#pragma unroll 4
    for (int hh = 0; hh < 64; hh++) {
        float w2 = d_Wp2T[hh * 256 + t];
        float wc = d_CT[hh * 256 + t];
        const float4* pr = (const float4*)&pe1s[hh * 16];
        float pv[16];
        *(float4*)&pv[0]  = pr[0];
        *(float4*)&pv[4]  = pr[1];
        *(float4*)&pv[8]  = pr[2];
        *(float4*)&pv[12] = pr[3];
#pragma unroll
        for (int j = 0; j < 16; j++) { pos[j] += w2 * pv[j]; cc[j] += wc * pv[j]; }
    }
    float qgd  = d_nodebuf[g * 768 + 256 + t];
    float bh   = d_biash[t];
    float bp2d = bp2[t];
#pragma unroll
    for (int j = 0; j < 16; j++) {
        int gm = (b << 12) + idxs[j];
        float kg = d_nodebuf[gm * 768 + 512 + t];
        float h1 = fmaxf(cc[j] + qgd - kg + bh, 0.f);
        h1s[t * 20 + j] = h1;
        pos[j] += bp2d;
    }
    __syncthreads();

    // phase D: attn[j][d] = W_g2 h1 + b_g2
    float attn[16];
#pragma unroll
    for (int j = 0; j < 16; j++) attn[j] = 0.f;
#pragma unroll 2
    for (int i = 0; i < 256; i++) {
        float w = d_Wg2T[i * 256 + t];
        const float4* hr = (const float4*)&h1s[i * 20];
        float hv[16];
        *(float4*)&hv[0]  = hr[0];
        *(float4*)&hv[4]  = hr[1];
        *(float4*)&hv[8]  = hr[2];
        *(float4*)&hv[12] = hr[3];
#pragma unroll
        for (int j = 0; j < 16; j++) attn[j] += w * hv[j];
    }

    // softmax over j per channel, then weighted sum of (v + pos)
    float bg = bg2[t];
    float mx = -3.4e38f;
#pragma unroll
    for (int j = 0; j < 16; j++) { attn[j] = (attn[j] + bg) * 0.0625f; mx = fmaxf(mx, attn[j]); }
    float sum = 0.f;
#pragma unroll
    for (int j = 0; j < 16; j++) { attn[j] = expf(attn[j] - mx); sum += attn[j]; }
    float inv = 1.f / sum;
    float acc = 0.f;
#pragma unroll
    for (int j = 0; j < 16; j++) {
        float w = attn[j] * inv;
        int gm = (b << 12) + idxs[j];
        float vv = d_nodebuf[gm * 768 + t];
        acc += w * (vv + pos[j]);
        out[OUT_ATTN_OFF + (g * 16 + j) * 256 + t] = w;
    }
    out[g * 256 + t] = acc;
}

// ---------------- launch ----------------
extern "C" void kernel_launch(void* const* d_in, const int* in_sizes, int n_in,
                              void* d_out, int out_size) {
    const float* feat   = (const float*)d_in[0];
    const float* xyz    = (const float*)d_in[1];
    const float* Wphi   = (const float*)d_in[2];
    const float* bphi   = (const float*)d_in[3];
    const float* Wpsi   = (const float*)d_in[4];
    const float* bpsi   = (const float*)d_in[5];
    const float* Walpha = (const float*)d_in[6];
    const float* balpha = (const float*)d_in[7];
    const float* Wg1    = (const float*)d_in[8];
    const float* bg1    = (const float*)d_in[9];
    const float* Wg2    = (const float*)d_in[10];
    const float* bg2    = (const float*)d_in[11];
    const float* Wp1    = (const float*)d_in[12];
    const float* bp1    = (const float*)d_in[13];
    const float* Wp2    = (const float*)d_in[14];
    const float* bp2    = (const float*)d_in[15];
    float* out = (float*)d_out;

    k_fold_AB<<<512, 256>>>(Wg1, Wphi, Wpsi);
    k_fold_copy<<<576, 256>>>(Walpha, Wg2, Wp2);
    k_fold_C<<<256, 64>>>(Wg1, Wp2);
    k_fold_bias<<<1, 256>>>(Wg1, bg1, bphi, bpsi, bp2);
    knn_kernel<<<64, 128>>>(xyz);
    node_gemm<<<dim3(12, 128), dim3(16, 16)>>>(feat, balpha);
    pt_main_kernel<<<8192, 256>>>(xyz, Wp1, bp1, bp2, bg2, out);
}

// round 3
// speedup vs baseline: 1.1024x; 1.1024x over previous
#include <cuda_runtime.h>
#include <math.h>

// Problem constants: B=2, N=4096, D=256, H=64, K=16
#define OUT_ATTN_OFF 2097152  // 2*4096*256

// ---------------- device scratch (no cudaMalloc allowed) ----------------
__device__ float d_Wstack[768 * 256];   // rows 0-255: W_alpha ; 256-511: A=Wg1*Wphi ; 512-767: Bm=Wg1*Wpsi
__device__ float d_Wg2T[256 * 256];     // Wg2T[i][d] = W_g2[d][i]
__device__ float d_Wp2T[64 * 256];      // Wp2T[h][d] = W_p2[d][h]
__device__ float d_CT[64 * 256];        // CT[h][d]   = (Wg1*Wp2)[d][h]
__device__ float d_biash[256];          // b_g1 + Wg1*(b_p2 + b_phi - b_psi)
__device__ float d_nodebuf[8192 * 768]; // per node: [v(256) | qg(256) | kg(256)]
__device__ int   d_knn[8192 * 16];

// ---------------- packed f32x2 helpers (Blackwell FFMA2) ----------------
__device__ __forceinline__ unsigned long long pack2(float x, float y) {
    unsigned long long r;
    asm("mov.b64 %0, {%1, %2};" : "=l"(r) : "f"(x), "f"(y));
    return r;
}
__device__ __forceinline__ void fma2(unsigned long long& d, unsigned long long a, unsigned long long b) {
    asm("fma.rn.f32x2 %0, %1, %2, %0;" : "+l"(d) : "l"(a), "l"(b));
}
__device__ __forceinline__ float2 unpack2(unsigned long long v) {
    float2 f;
    asm("mov.b64 {%0, %1}, %2;" : "=f"(f.x), "=f"(f.y) : "l"(v));
    return f;
}

// ---------------- weight folding ----------------
__global__ void k_fold_AB(const float* __restrict__ Wg1,
                          const float* __restrict__ Wphi,
                          const float* __restrict__ Wpsi) {
    __shared__ float row[256];
    int r = blockIdx.x, t = threadIdx.x;
    int src = (r < 256) ? r : r - 256;
    row[t] = Wg1[src * 256 + t];
    __syncthreads();
    const float* W = (r < 256) ? Wphi : Wpsi;
    float acc = 0.f;
    for (int i = 0; i < 256; i++) acc += row[i] * W[i * 256 + t];
    d_Wstack[(256 + r) * 256 + t] = acc;
}

__global__ void k_fold_copy(const float* __restrict__ Walpha,
                            const float* __restrict__ Wg2,
                            const float* __restrict__ Wp2) {
    int blk = blockIdx.x, t = threadIdx.x;
    if (blk < 256) {
        d_Wstack[blk * 256 + t] = Walpha[blk * 256 + t];
    } else if (blk < 512) {
        int dd = blk - 256;
        d_Wg2T[t * 256 + dd] = Wg2[dd * 256 + t];
    } else {
        int idx = (blk - 512) * 256 + t;   // over 256*64 elements
        int dd = idx >> 6, h = idx & 63;
        d_Wp2T[h * 256 + dd] = Wp2[idx];   // Wp2[dd][h]
    }
}

__global__ void k_fold_C(const float* __restrict__ Wg1,
                         const float* __restrict__ Wp2) {
    __shared__ float row[256];
    int o = blockIdx.x, hh = threadIdx.x;  // 64 threads
    for (int i = hh; i < 256; i += 64) row[i] = Wg1[o * 256 + i];
    __syncthreads();
    float acc = 0.f;
    for (int tt = 0; tt < 256; tt++) acc += row[tt] * Wp2[tt * 64 + hh];
    d_CT[hh * 256 + o] = acc;
}

// parallel bias fold: one warp per output channel
__global__ void k_fold_bias(const float* __restrict__ Wg1,
                            const float* __restrict__ bg1,
                            const float* __restrict__ bphi,
                            const float* __restrict__ bpsi,
                            const float* __restrict__ bp2) {
    __shared__ float combo[256];
    int t = threadIdx.x;                 // 256 threads, 8 warps
    combo[t] = bp2[t] + bphi[t] - bpsi[t];
    __syncthreads();
    int wid = t >> 5, lane = t & 31;
    int o = blockIdx.x * 8 + wid;        // 32 blocks * 8 warps = 256 outputs
    float acc = 0.f;
#pragma unroll
    for (int i = lane; i < 256; i += 32) acc += Wg1[o * 256 + i] * combo[i];
#pragma unroll
    for (int off = 16; off > 0; off >>= 1) acc += __shfl_down_sync(0xffffffff, acc, off);
    if (lane == 0) d_biash[o] = bg1[o] + acc;
}

// ---------------- KNN: brute force top-16 ----------------
__global__ void knn_kernel(const float* __restrict__ xyz) {
    __shared__ float tx[256], tys[256], tz[256], tsq[256];
    int gq = blockIdx.x * 64 + threadIdx.x;   // 128 blocks * 64 threads = 8192
    int b = gq >> 12;
    float qx = xyz[gq * 3 + 0], qy = xyz[gq * 3 + 1], qz = xyz[gq * 3 + 2];
    float sqq = qx * qx + qy * qy + qz * qz;
    float bd[16];
    int   bi[16];
#pragma unroll
    for (int j = 0; j < 16; j++) { bd[j] = 3.4e38f; bi[j] = 0x7fffffff; }

    for (int tile = 0; tile < 16; tile++) {
        int base = tile * 256;
        __syncthreads();
        for (int s = threadIdx.x; s < 256; s += 64) {
            int g = (b << 12) + base + s;
            float x = xyz[g * 3 + 0], y = xyz[g * 3 + 1], z = xyz[g * 3 + 2];
            tx[s] = x; tys[s] = y; tz[s] = z;
            tsq[s] = x * x + y * y + z * z;
        }
        __syncthreads();
#pragma unroll 2
        for (int s = 0; s < 256; s++) {
            float dot = qx * tx[s] + qy * tys[s] + qz * tz[s];
            float d2 = sqq + tsq[s] - 2.f * dot;
            int m = base + s;
            if (d2 < bd[15] || (d2 == bd[15] && m < bi[15])) {
                bd[15] = d2; bi[15] = m;
#pragma unroll
                for (int u = 15; u >= 1; --u) {
                    bool sw = bd[u] < bd[u - 1] || (bd[u] == bd[u - 1] && bi[u] < bi[u - 1]);
                    if (sw) {
                        float td = bd[u]; bd[u] = bd[u - 1]; bd[u - 1] = td;
                        int ti = bi[u];  bi[u] = bi[u - 1];  bi[u - 1] = ti;
                    }
                }
            }
        }
    }
#pragma unroll
    for (int j = 0; j < 16; j++) d_knn[gq * 16 + j] = bi[j];
}

// ---------------- per-node GEMM: nodebuf = feat @ Wstack^T (+bias on v block) ----------------
__global__ void node_gemm(const float* __restrict__ feat,
                          const float* __restrict__ balpha) {
    __shared__ float As[16][68];
    __shared__ float Bs[16][68];
    int tx = threadIdx.x, ty = threadIdx.y;
    int t = ty * 16 + tx;
    int o0 = blockIdx.x * 64, m0 = blockIdx.y * 64;
    unsigned long long acc2[4][2];
#pragma unroll
    for (int i = 0; i < 4; i++) { acc2[i][0] = 0ull; acc2[i][1] = 0ull; }
    int lm = t >> 2, lk = (t & 3) * 4;
    for (int k0 = 0; k0 < 256; k0 += 16) {
        float4 fa = *(const float4*)&feat[(m0 + lm) * 256 + k0 + lk];
        float4 fb = *(const float4*)&d_Wstack[(o0 + lm) * 256 + k0 + lk];
        __syncthreads();
        As[lk + 0][lm] = fa.x; As[lk + 1][lm] = fa.y; As[lk + 2][lm] = fa.z; As[lk + 3][lm] = fa.w;
        Bs[lk + 0][lm] = fb.x; Bs[lk + 1][lm] = fb.y; Bs[lk + 2][lm] = fb.z; Bs[lk + 3][lm] = fb.w;
        __syncthreads();
#pragma unroll
        for (int kk = 0; kk < 16; kk++) {
            float4 a = *(const float4*)&As[kk][ty * 4];
            // bb as two packed f32x2 (16B-aligned: row stride 272B, col offset 16B)
            const unsigned long long* bp = (const unsigned long long*)&Bs[kk][tx * 4];
            unsigned long long b01 = bp[0], b23 = bp[1];
            unsigned long long ax = pack2(a.x, a.x), ay = pack2(a.y, a.y);
            unsigned long long az = pack2(a.z, a.z), aw = pack2(a.w, a.w);
            fma2(acc2[0][0], ax, b01); fma2(acc2[0][1], ax, b23);
            fma2(acc2[1][0], ay, b01); fma2(acc2[1][1], ay, b23);
            fma2(acc2[2][0], az, b01); fma2(acc2[2][1], az, b23);
            fma2(acc2[3][0], aw, b01); fma2(acc2[3][1], aw, b23);
        }
    }
#pragma unroll
    for (int i = 0; i < 4; i++) {
        int m = m0 + ty * 4 + i;
        float2 p0 = unpack2(acc2[i][0]);
        float2 p1 = unpack2(acc2[i][1]);
        float vals[4] = { p0.x, p0.y, p1.x, p1.y };
#pragma unroll
        for (int j = 0; j < 4; j++) {
            int o = o0 + tx * 4 + j;
            float bias = (o < 256) ? balpha[o] : 0.f;
            d_nodebuf[m * 768 + o] = vals[j] + bias;
        }
    }
}

// ---------------- main fused attention kernel: one block per (b,n) ----------------
__global__ void __launch_bounds__(256) pt_main_kernel(
    const float* __restrict__ xyz,
    const float* __restrict__ Wp1, const float* __restrict__ bp1,
    const float* __restrict__ bp2, const float* __restrict__ bg2,
    float* __restrict__ out) {
    __shared__ __align__(16) float pe1s[64 * 16];   // pe1s[h][j], row = 64B
    __shared__ __align__(16) float h1s[256 * 20];   // h1s[i][j], stride 20 floats = 80B (16B-aligned rows)
    __shared__ float nx[16], ny[16], nz[16];
    __shared__ int idxs[16];
    __shared__ float q3[3];

    int g = blockIdx.x;      // global point 0..8191
    int b = g >> 12;
    int t = threadIdx.x;     // channel d

    if (t < 16) idxs[t] = d_knn[g * 16 + t];
    if (t < 3)  q3[t] = xyz[g * 3 + t];
    __syncthreads();
    if (t < 48) {
        int j = t / 3, c = t % 3;
        float v = xyz[((b << 12) + idxs[j]) * 3 + c];
        if (c == 0) nx[j] = v; else if (c == 1) ny[j] = v; else nz[j] = v;
    }
    __syncthreads();

    // phase B: pe1[j][h] = relu(W_p1 rel + b_p1)
#pragma unroll
    for (int r = 0; r < 4; r++) {
        int idx = r * 256 + t;
        int j = idx & 15, hh = idx >> 4;
        float rx = q3[0] - nx[j], ry = q3[1] - ny[j], rz = q3[2] - nz[j];
        float v = bp1[hh] + Wp1[hh * 3 + 0] * rx + Wp1[hh * 3 + 1] * ry + Wp1[hh * 3 + 2] * rz;
        pe1s[hh * 16 + j] = fmaxf(v, 0.f);
    }
    __syncthreads();

    // phase C: pos[j] = W_p2 pe1, cc[j] = C pe1  (packed f32x2)
    unsigned long long pos2[8], cc2[8];
#pragma unroll
    for (int jj = 0; jj < 8; jj++) { pos2[jj] = 0ull; cc2[jj] = 0ull; }
#pragma unroll 2
    for (int hh = 0; hh < 64; hh++) {
        float w2 = d_Wp2T[hh * 256 + t];
        float wc = d_CT[hh * 256 + t];
        unsigned long long w2p = pack2(w2, w2);
        unsigned long long wcp = pack2(wc, wc);
        const ulonglong2* pr = (const ulonglong2*)&pe1s[hh * 16];
        ulonglong2 a0 = pr[0], a1 = pr[1], a2 = pr[2], a3 = pr[3];
        fma2(pos2[0], w2p, a0.x); fma2(pos2[1], w2p, a0.y);
        fma2(pos2[2], w2p, a1.x); fma2(pos2[3], w2p, a1.y);
        fma2(pos2[4], w2p, a2.x); fma2(pos2[5], w2p, a2.y);
        fma2(pos2[6], w2p, a3.x); fma2(pos2[7], w2p, a3.y);
        fma2(cc2[0], wcp, a0.x); fma2(cc2[1], wcp, a0.y);
        fma2(cc2[2], wcp, a1.x); fma2(cc2[3], wcp, a1.y);
        fma2(cc2[4], wcp, a2.x); fma2(cc2[5], wcp, a2.y);
        fma2(cc2[6], wcp, a3.x); fma2(cc2[7], wcp, a3.y);
    }
    float pos[16], cc[16];
#pragma unroll
    for (int jj = 0; jj < 8; jj++) {
        float2 p = unpack2(pos2[jj]); pos[2 * jj] = p.x; pos[2 * jj + 1] = p.y;
        float2 c = unpack2(cc2[jj]);  cc[2 * jj] = c.x;  cc[2 * jj + 1] = c.y;
    }

    float qgd  = d_nodebuf[g * 768 + 256 + t];
    float bh   = d_biash[t];
    float bp2d = bp2[t];
#pragma unroll
    for (int j = 0; j < 16; j++) {
        int gm = (b << 12) + idxs[j];
        float kg = d_nodebuf[gm * 768 + 512 + t];
        float h1 = fmaxf(cc[j] + qgd - kg + bh, 0.f);
        h1s[t * 20 + j] = h1;
        pos[j] += bp2d;
    }
    __syncthreads();

    // phase D: attn[j][d] = W_g2 h1 + b_g2  (packed f32x2)
    unsigned long long at2[8];
#pragma unroll
    for (int jj = 0; jj < 8; jj++) at2[jj] = 0ull;
#pragma unroll 2
    for (int i = 0; i < 256; i++) {
        float w = d_Wg2T[i * 256 + t];
        unsigned long long wp = pack2(w, w);
        const ulonglong2* hr = (const ulonglong2*)&h1s[i * 20];
        ulonglong2 a0 = hr[0], a1 = hr[1], a2 = hr[2], a3 = hr[3];
        fma2(at2[0], wp, a0.x); fma2(at2[1], wp, a0.y);
        fma2(at2[2], wp, a1.x); fma2(at2[3], wp, a1.y);
        fma2(at2[4], wp, a2.x); fma2(at2[5], wp, a2.y);
        fma2(at2[6], wp, a3.x); fma2(at2[7], wp, a3.y);
    }
    float attn[16];
#pragma unroll
    for (int jj = 0; jj < 8; jj++) {
        float2 a = unpack2(at2[jj]); attn[2 * jj] = a.x; attn[2 * jj + 1] = a.y;
    }

    // softmax over j per channel, then weighted sum of (v + pos)
    float bg = bg2[t];
    float mx = -3.4e38f;
#pragma unroll
    for (int j = 0; j < 16; j++) { attn[j] = (attn[j] + bg) * 0.0625f; mx = fmaxf(mx, attn[j]); }
    float sum = 0.f;
#pragma unroll
    for (int j = 0; j < 16; j++) { attn[j] = expf(attn[j] - mx); sum += attn[j]; }
    float inv = 1.f / sum;
    float acc = 0.f;
#pragma unroll
    for (int j = 0; j < 16; j++) {
        float w = attn[j] * inv;
        int gm = (b << 12) + idxs[j];
        float vv = d_nodebuf[gm * 768 + t];
        acc += w * (vv + pos[j]);
        out[OUT_ATTN_OFF + (g * 16 + j) * 256 + t] = w;
    }
    out[g * 256 + t] = acc;
}

// ---------------- launch ----------------
extern "C" void kernel_launch(void* const* d_in, const int* in_sizes, int n_in,
                              void* d_out, int out_size) {
    const float* feat   = (const float*)d_in[0];
    const float* xyz    = (const float*)d_in[1];
    const float* Wphi   = (const float*)d_in[2];
    const float* bphi   = (const float*)d_in[3];
    const float* Wpsi   = (const float*)d_in[4];
    const float* bpsi   = (const float*)d_in[5];
    const float* Walpha = (const float*)d_in[6];
    const float* balpha = (const float*)d_in[7];
    const float* Wg1    = (const float*)d_in[8];
    const float* bg1    = (const float*)d_in[9];
    const float* Wg2    = (const float*)d_in[10];
    const float* bg2    = (const float*)d_in[11];
    const float* Wp1    = (const float*)d_in[12];
    const float* bp1    = (const float*)d_in[13];
    const float* Wp2    = (const float*)d_in[14];
    const float* bp2    = (const float*)d_in[15];
    float* out = (float*)d_out;

    k_fold_AB<<<512, 256>>>(Wg1, Wphi, Wpsi);
    k_fold_copy<<<576, 256>>>(Walpha, Wg2, Wp2);
    k_fold_C<<<256, 64>>>(Wg1, Wp2);
    k_fold_bias<<<32, 256>>>(Wg1, bg1, bphi, bpsi, bp2);
    knn_kernel<<<128, 64>>>(xyz);
    node_gemm<<<dim3(12, 128), dim3(16, 16)>>>(feat, balpha);
    pt_main_kernel<<<8192, 256>>>(xyz, Wp1, bp1, bp2, bg2, out);
}